// round 15
// baseline (speedup 1.0000x reference)
#include <cuda_runtime.h>
#include <math.h>
#include <stdint.h>

// Problem shape (fixed by reference setup_inputs)
#define BB 8
#define DD 64
#define HW (256 * 512)        // 131072
#define PIXELS (BB * HW)      // 1048576
#define TPB 128
#define PPT 8                 // pixels per thread
#define NBLOCKS (PIXELS / PPT / TPB)   // 1024
#define TILE 1024             // floats per block per d-slice (4 KB)

#define SUPER  4              // d-slices per bulk group (16 KB)
#define NSUPER (DD / SUPER)   // 16
#define NBUF   2              // ping-pong

#define LOG2E     1.4426950408889634f
#define INV_LOG2E 0.6931471805599453f
#define TWO_LOG2E 2.8853900817779268f
#define INV_1ME2  1.1565176427496657f   // 1/(1-e^-2)

// Allocation-free scratch
__device__ float        g_partial[NBLOCKS];
__device__ int          g_pcnt[NBLOCKS];
__device__ unsigned int g_done;

__device__ __forceinline__ float ex2(float x) {
    float r; asm("ex2.approx.f32 %0, %1;" : "=f"(r) : "f"(x)); return r;
}
__device__ __forceinline__ float lg2(float x) {
    float r; asm("lg2.approx.f32 %0, %1;" : "=f"(r) : "f"(x)); return r;
}
__device__ __forceinline__ void mbar_init(uint32_t addr, uint32_t count) {
    asm volatile("mbarrier.init.shared.b64 [%0], %1;" :: "r"(addr), "r"(count) : "memory");
}
__device__ __forceinline__ void mbar_expect_tx(uint32_t addr, uint32_t bytes) {
    asm volatile("mbarrier.arrive.expect_tx.shared.b64 _, [%0], %1;"
                 :: "r"(addr), "r"(bytes) : "memory");
}
__device__ __forceinline__ void bulk_g2s(uint32_t dst, const void* src,
                                         uint32_t bytes, uint32_t mbar) {
    asm volatile("cp.async.bulk.shared::cta.global.mbarrier::complete_tx::bytes "
                 "[%0], [%1], %2, [%3];"
                 :: "r"(dst), "l"(src), "r"(bytes), "r"(mbar) : "memory");
}
__device__ __forceinline__ void mbar_wait(uint32_t addr, uint32_t parity) {
    asm volatile(
        "{\n\t.reg .pred P;\n"
        "W%=:\n\t"
        "mbarrier.try_wait.parity.shared.b64 P, [%0], %1;\n\t"
        "@P bra D%=;\n\t"
        "bra W%=;\n"
        "D%=:\n\t}"
        :: "r"(addr), "r"(parity) : "memory");
}

// entropy = (lg2(se) - sptx/spt) / log2e
//   se = sum_d 2^{x*log2e};  w = 2^{-|dl-gl|};  sptx = sum_d w*(x*log2e)
//   gl = gt*log2e (inf -> w = 0, self-masking), dl = 2d*log2e (uniform carried)
// spt closed form (two geometric series), epilogue-only.
__global__ void __launch_bounds__(TPB, 7)
sce_fused_kernel(const float* __restrict__ sim, const float* __restrict__ gt,
                 float* __restrict__ out) {
    __shared__ __align__(16) float data[NBUF][SUPER * TILE];   // 32 KB
    __shared__ __align__(8) unsigned long long mbar[NBUF];

    const int tid = blockIdx.x * TPB + threadIdx.x;
    const int p   = tid * PPT;
    const int p0  = blockIdx.x * (TPB * PPT);
    const int b   = p0 / HW;
    const int rem = p0 - b * HW;

    const float* gsrc = sim + (size_t)b * DD * HW + rem;   // + d*HW per slice

    const uint32_t mb0 = (uint32_t)__cvta_generic_to_shared(&mbar[0]);
    const uint32_t mb1 = (uint32_t)__cvta_generic_to_shared(&mbar[1]);
    const uint32_t dsm = (uint32_t)__cvta_generic_to_shared(&data[0][0]);

    if (threadIdx.x == 0) { mbar_init(mb0, 1); mbar_init(mb1, 1); }
    __syncthreads();

    // Prologue: producer loads super 0 into buf 0
    if (threadIdx.x == 0) {
        mbar_expect_tx(mb0, SUPER * TILE * 4);
        #pragma unroll
        for (int k = 0; k < SUPER; ++k)
            bulk_g2s(dsm + k * (TILE * 4), gsrc + (size_t)k * HW, TILE * 4, mb0);
    }

    // Per-pixel constants
    float gl[PPT], se[PPT], sptx[PPT];
    {
        const float4 g0 = *(const float4*)(gt + p);
        const float4 g1 = *(const float4*)(gt + p + 4);
        gl[0]=g0.x*LOG2E; gl[1]=g0.y*LOG2E; gl[2]=g0.z*LOG2E; gl[3]=g0.w*LOG2E;
        gl[4]=g1.x*LOG2E; gl[5]=g1.y*LOG2E; gl[6]=g1.z*LOG2E; gl[7]=g1.w*LOG2E;
    }
    #pragma unroll
    for (int j = 0; j < PPT; ++j) { se[j] = 0.f; sptx[j] = 0.f; }

    float dl = 0.0f;   // 2d * log2e, uniform

    for (int s = 0; s < NSUPER; ++s) {
        // All threads finished reading buffer (s-1)&1 (super s-1) -> safe to refill
        __syncthreads();
        if (threadIdx.x == 0 && s + 1 < NSUPER) {
            const int nb = (s + 1) & 1;
            const uint32_t mbn = nb ? mb1 : mb0;
            mbar_expect_tx(mbn, SUPER * TILE * 4);
            const float* src = gsrc + (size_t)(s + 1) * SUPER * HW;
            #pragma unroll
            for (int k = 0; k < SUPER; ++k)
                bulk_g2s(dsm + nb * (SUPER * TILE * 4) + k * (TILE * 4),
                         src + (size_t)k * HW, TILE * 4, mbn);
        }
        // Wait for super s
        mbar_wait((s & 1) ? mb1 : mb0, (uint32_t)((s >> 1) & 1));

        const float4* rowb = (const float4*)&data[s & 1][0];
        #pragma unroll
        for (int k = 0; k < SUPER; ++k) {
            const float4 x0 = rowb[k * (TILE / 4) + threadIdx.x * 2 + 0];
            const float4 x1 = rowb[k * (TILE / 4) + threadIdx.x * 2 + 1];

            float xl;
            xl = x0.x * LOG2E; se[0] += ex2(xl); sptx[0] += ex2(-fabsf(dl - gl[0])) * xl;
            xl = x0.y * LOG2E; se[1] += ex2(xl); sptx[1] += ex2(-fabsf(dl - gl[1])) * xl;
            xl = x0.z * LOG2E; se[2] += ex2(xl); sptx[2] += ex2(-fabsf(dl - gl[2])) * xl;
            xl = x0.w * LOG2E; se[3] += ex2(xl); sptx[3] += ex2(-fabsf(dl - gl[3])) * xl;
            xl = x1.x * LOG2E; se[4] += ex2(xl); sptx[4] += ex2(-fabsf(dl - gl[4])) * xl;
            xl = x1.y * LOG2E; se[5] += ex2(xl); sptx[5] += ex2(-fabsf(dl - gl[5])) * xl;
            xl = x1.z * LOG2E; se[6] += ex2(xl); sptx[6] += ex2(-fabsf(dl - gl[6])) * xl;
            xl = x1.w * LOG2E; se[7] += ex2(xl); sptx[7] += ex2(-fabsf(dl - gl[7])) * xl;

            dl += TWO_LOG2E;
        }
    }

    float local = 0.f;
    int   cnt   = 0;
    #pragma unroll
    for (int j = 0; j < PPT; ++j) {
        if (isfinite(gl[j])) {
            const float gv  = gl[j] * INV_LOG2E;
            const float m   = floorf(gv * 0.5f);
            const float a   = gv - 2.0f * m;
            const float spt = (__expf(-a) - __expf(-gv - 2.0f)
                             + __expf(a - 2.0f) - __expf(gv - 128.0f)) * INV_1ME2;
            local += (lg2(se[j]) - __fdividef(sptx[j], spt)) * INV_LOG2E;
            cnt   += 1;
        }
    }

    // Block reduce (4 warps)
    #pragma unroll
    for (int o = 16; o > 0; o >>= 1) {
        local += __shfl_down_sync(0xffffffffu, local, o);
        cnt   += __shfl_down_sync(0xffffffffu, cnt, o);
    }
    __shared__ float ssum[4];
    __shared__ int   scnt[4];
    __shared__ bool  isLast;
    const int lane = threadIdx.x & 31;
    const int wid  = threadIdx.x >> 5;
    if (lane == 0) { ssum[wid] = local; scnt[wid] = cnt; }
    __syncthreads();
    if (wid == 0) {
        local = (lane < 4) ? ssum[lane] : 0.f;
        cnt   = (lane < 4) ? scnt[lane] : 0;
        #pragma unroll
        for (int o = 2; o > 0; o >>= 1) {
            local += __shfl_down_sync(0xffffffffu, local, o);
            cnt   += __shfl_down_sync(0xffffffffu, cnt, o);
        }
        if (lane == 0) {
            g_partial[blockIdx.x] = local;
            g_pcnt[blockIdx.x]    = cnt;
            __threadfence();
            unsigned int prev = atomicAdd(&g_done, 1u);
            isLast = (prev == (unsigned int)(gridDim.x - 1));
        }
    }
    __syncthreads();

    // Last finished block reduces all partials
    if (isLast) {
        __threadfence();
        const volatile float* vp = g_partial;
        const volatile int*   vc = g_pcnt;
        float s = 0.f;
        int   c = 0;
        #pragma unroll
        for (int k = 0; k < NBLOCKS / TPB; ++k) {
            s += vp[threadIdx.x + k * TPB];
            c += vc[threadIdx.x + k * TPB];
        }
        #pragma unroll
        for (int o = 16; o > 0; o >>= 1) {
            s += __shfl_down_sync(0xffffffffu, s, o);
            c += __shfl_down_sync(0xffffffffu, c, o);
        }
        if (lane == 0) { ssum[wid] = s; scnt[wid] = c; }
        __syncthreads();
        if (wid == 0) {
            s = (lane < 4) ? ssum[lane] : 0.f;
            c = (lane < 4) ? scnt[lane] : 0;
            #pragma unroll
            for (int o = 2; o > 0; o >>= 1) {
                s += __shfl_down_sync(0xffffffffu, s, o);
                c += __shfl_down_sync(0xffffffffu, c, o);
            }
            if (lane == 0) {
                out[0] = s / (float)c;
                g_done = 0;
            }
        }
    }
}

extern "C" void kernel_launch(void* const* d_in, const int* in_sizes, int n_in,
                              void* d_out, int out_size) {
    const float* sim = (const float*)d_in[0];
    const float* gt  = (const float*)d_in[1];
    float* out       = (float*)d_out;

    sce_fused_kernel<<<NBLOCKS, TPB>>>(sim, gt, out);
}

// round 16
// speedup vs baseline: 1.1941x; 1.1941x over previous
#include <cuda_runtime.h>
#include <cuda_pipeline.h>
#include <math.h>

// Problem shape (fixed by reference setup_inputs)
#define BB 8
#define DD 64
#define HW (256 * 512)        // 131072
#define PIXELS (BB * HW)      // 1048576
#define TPB 128
#define PPT 8                 // pixels per thread
#define NBLOCKS (PIXELS / PPT / TPB)   // 1024

#define STAGES 6              // 24 KB staging -> 7 blocks/SM -> single wave
// Group = 2 slices; 3 groups; prefetch distance = 2 groups (4 slices)

#define LOG2E     1.4426950408889634f
#define INV_LOG2E 0.6931471805599453f
#define TWO_LOG2E 2.8853900817779268f
#define FOUR_LOG2E 5.7707801635558536f
#define INV_1ME2  1.1565176427496657f   // 1/(1-e^-2)

// Allocation-free scratch
__device__ float        g_partial[NBLOCKS];
__device__ int          g_pcnt[NBLOCKS];
__device__ unsigned int g_done;

__device__ __forceinline__ float ex2(float x) {
    float r; asm("ex2.approx.f32 %0, %1;" : "=f"(r) : "f"(x)); return r;
}
__device__ __forceinline__ float lg2(float x) {
    float r; asm("lg2.approx.f32 %0, %1;" : "=f"(r) : "f"(x)); return r;
}

// entropy = (lg2(se) - sptx/spt) / log2e
//   se = sum_d 2^{x*log2e};  w = 2^{-|dl-gl|};  sptx = sum_d w*(x*log2e)
//   gl = gt*log2e (inf -> w=0 self-masking); dl = 2d*log2e (uniform carried)
// spt closed form (two geometric series), epilogue-only.
__global__ void __launch_bounds__(TPB, 7)
sce_fused_kernel(const float* __restrict__ sim, const float* __restrict__ gt,
                 float* __restrict__ out) {
    __shared__ __align__(16) float4 buf[STAGES][TPB * 2];   // 24 KB staging

    const int tid = blockIdx.x * TPB + threadIdx.x;
    const int p   = tid * PPT;
    const int b   = p / HW;
    const int rem = p - b * HW;

    const float4* simv = (const float4*)(sim + (size_t)b * DD * HW + rem);

    // Per-pixel constants
    float gl[PPT], se[PPT], sptx[PPT];
    {
        const float4 g0 = *(const float4*)(gt + p);
        const float4 g1 = *(const float4*)(gt + p + 4);
        gl[0]=g0.x*LOG2E; gl[1]=g0.y*LOG2E; gl[2]=g0.z*LOG2E; gl[3]=g0.w*LOG2E;
        gl[4]=g1.x*LOG2E; gl[5]=g1.y*LOG2E; gl[6]=g1.z*LOG2E; gl[7]=g1.w*LOG2E;
    }
    #pragma unroll
    for (int j = 0; j < PPT; ++j) { se[j] = 0.f; sptx[j] = 0.f; }

    // Prologue: prefetch groups 0 and 1 (slices 0..3), one commit per group
    const float4* srcp = simv;
    #pragma unroll
    for (int gp = 0; gp < 2; ++gp) {
        #pragma unroll
        for (int k = 0; k < 2; ++k) {
            const int s = gp * 2 + k;
            __pipeline_memcpy_async(&buf[s][threadIdx.x * 2 + 0], srcp + 0, 16);
            __pipeline_memcpy_async(&buf[s][threadIdx.x * 2 + 1], srcp + 1, 16);
            srcp += HW / 4;
        }
        __pipeline_commit();
    }
    // srcp now at slice 4

    float dl = 0.0f;   // 2d*log2e, uniform
    int   st = 0;      // read stage of first slice in current group
    int   sn = 4;      // write stage of first slice in group g+2

    #pragma unroll 1
    for (int g = 0; g < DD / 2; ++g) {        // 32 iterations, 2 slices each
        __pipeline_wait_prior(1);             // group g complete
        const float4 a0 = buf[st][threadIdx.x * 2 + 0];
        const float4 a1 = buf[st][threadIdx.x * 2 + 1];
        const int st1 = (st + 1 == STAGES) ? 0 : st + 1;
        const float4 b0 = buf[st1][threadIdx.x * 2 + 0];
        const float4 b1 = buf[st1][threadIdx.x * 2 + 1];

        // Prefetch group g+2 (slices 2g+4, 2g+5) into stages sn, sn+1
        if (g < DD / 2 - 2) {
            __pipeline_memcpy_async(&buf[sn][threadIdx.x * 2 + 0], srcp + 0, 16);
            __pipeline_memcpy_async(&buf[sn][threadIdx.x * 2 + 1], srcp + 1, 16);
            srcp += HW / 4;
            const int sn1 = (sn + 1 == STAGES) ? 0 : sn + 1;
            __pipeline_memcpy_async(&buf[sn1][threadIdx.x * 2 + 0], srcp + 0, 16);
            __pipeline_memcpy_async(&buf[sn1][threadIdx.x * 2 + 1], srcp + 1, 16);
            srcp += HW / 4;
        }
        __pipeline_commit();                  // keep group counting aligned

        float xl;
        // slice 2g  (offset dl)
        xl = a0.x * LOG2E; se[0] += ex2(xl); sptx[0] += ex2(-fabsf(dl - gl[0])) * xl;
        xl = a0.y * LOG2E; se[1] += ex2(xl); sptx[1] += ex2(-fabsf(dl - gl[1])) * xl;
        xl = a0.z * LOG2E; se[2] += ex2(xl); sptx[2] += ex2(-fabsf(dl - gl[2])) * xl;
        xl = a0.w * LOG2E; se[3] += ex2(xl); sptx[3] += ex2(-fabsf(dl - gl[3])) * xl;
        xl = a1.x * LOG2E; se[4] += ex2(xl); sptx[4] += ex2(-fabsf(dl - gl[4])) * xl;
        xl = a1.y * LOG2E; se[5] += ex2(xl); sptx[5] += ex2(-fabsf(dl - gl[5])) * xl;
        xl = a1.z * LOG2E; se[6] += ex2(xl); sptx[6] += ex2(-fabsf(dl - gl[6])) * xl;
        xl = a1.w * LOG2E; se[7] += ex2(xl); sptx[7] += ex2(-fabsf(dl - gl[7])) * xl;
        // slice 2g+1 (offset dl + 2*log2e)
        const float dl1 = dl + TWO_LOG2E;
        xl = b0.x * LOG2E; se[0] += ex2(xl); sptx[0] += ex2(-fabsf(dl1 - gl[0])) * xl;
        xl = b0.y * LOG2E; se[1] += ex2(xl); sptx[1] += ex2(-fabsf(dl1 - gl[1])) * xl;
        xl = b0.z * LOG2E; se[2] += ex2(xl); sptx[2] += ex2(-fabsf(dl1 - gl[2])) * xl;
        xl = b0.w * LOG2E; se[3] += ex2(xl); sptx[3] += ex2(-fabsf(dl1 - gl[3])) * xl;
        xl = b1.x * LOG2E; se[4] += ex2(xl); sptx[4] += ex2(-fabsf(dl1 - gl[4])) * xl;
        xl = b1.y * LOG2E; se[5] += ex2(xl); sptx[5] += ex2(-fabsf(dl1 - gl[5])) * xl;
        xl = b1.z * LOG2E; se[6] += ex2(xl); sptx[6] += ex2(-fabsf(dl1 - gl[6])) * xl;
        xl = b1.w * LOG2E; se[7] += ex2(xl); sptx[7] += ex2(-fabsf(dl1 - gl[7])) * xl;

        dl += FOUR_LOG2E;
        st = (st + 2 >= STAGES) ? st + 2 - STAGES : st + 2;
        sn = (sn + 2 >= STAGES) ? sn + 2 - STAGES : sn + 2;
    }

    float local = 0.f;
    int   cnt   = 0;
    #pragma unroll
    for (int j = 0; j < PPT; ++j) {
        if (isfinite(gl[j])) {
            const float gv  = gl[j] * INV_LOG2E;
            const float m   = floorf(gv * 0.5f);
            const float a   = gv - 2.0f * m;
            const float spt = (__expf(-a) - __expf(-gv - 2.0f)
                             + __expf(a - 2.0f) - __expf(gv - 128.0f)) * INV_1ME2;
            local += (lg2(se[j]) - __fdividef(sptx[j], spt)) * INV_LOG2E;
            cnt   += 1;
        }
    }

    // Block reduce (4 warps)
    #pragma unroll
    for (int o = 16; o > 0; o >>= 1) {
        local += __shfl_down_sync(0xffffffffu, local, o);
        cnt   += __shfl_down_sync(0xffffffffu, cnt, o);
    }
    __shared__ float ssum[4];
    __shared__ int   scnt[4];
    __shared__ bool  isLast;
    const int lane = threadIdx.x & 31;
    const int wid  = threadIdx.x >> 5;
    if (lane == 0) { ssum[wid] = local; scnt[wid] = cnt; }
    __syncthreads();
    if (wid == 0) {
        local = (lane < 4) ? ssum[lane] : 0.f;
        cnt   = (lane < 4) ? scnt[lane] : 0;
        #pragma unroll
        for (int o = 2; o > 0; o >>= 1) {
            local += __shfl_down_sync(0xffffffffu, local, o);
            cnt   += __shfl_down_sync(0xffffffffu, cnt, o);
        }
        if (lane == 0) {
            g_partial[blockIdx.x] = local;
            g_pcnt[blockIdx.x]    = cnt;
            __threadfence();
            unsigned int prev = atomicAdd(&g_done, 1u);
            isLast = (prev == (unsigned int)(gridDim.x - 1));
        }
    }
    __syncthreads();

    // Last finished block reduces all partials
    if (isLast) {
        __threadfence();
        const volatile float* vp = g_partial;
        const volatile int*   vc = g_pcnt;
        float s = 0.f;
        int   c = 0;
        #pragma unroll
        for (int k = 0; k < NBLOCKS / TPB; ++k) {
            s += vp[threadIdx.x + k * TPB];
            c += vc[threadIdx.x + k * TPB];
        }
        #pragma unroll
        for (int o = 16; o > 0; o >>= 1) {
            s += __shfl_down_sync(0xffffffffu, s, o);
            c += __shfl_down_sync(0xffffffffu, c, o);
        }
        if (lane == 0) { ssum[wid] = s; scnt[wid] = c; }
        __syncthreads();
        if (wid == 0) {
            s = (lane < 4) ? ssum[lane] : 0.f;
            c = (lane < 4) ? scnt[lane] : 0;
            #pragma unroll
            for (int o = 2; o > 0; o >>= 1) {
                s += __shfl_down_sync(0xffffffffu, s, o);
                c += __shfl_down_sync(0xffffffffu, c, o);
            }
            if (lane == 0) {
                out[0] = s / (float)c;
                g_done = 0;
            }
        }
    }
}

extern "C" void kernel_launch(void* const* d_in, const int* in_sizes, int n_in,
                              void* d_out, int out_size) {
    const float* sim = (const float*)d_in[0];
    const float* gt  = (const float*)d_in[1];
    float* out       = (float*)d_out;

    sce_fused_kernel<<<NBLOCKS, TPB>>>(sim, gt, out);
}